// round 1
// baseline (speedup 1.0000x reference)
#include <cuda_runtime.h>
#include <math.h>

#define Bc 4
#define Sc 2048
#define Ec 768
#define Hc 12
#define Dc 64
#define E3 2304
#define NGLOB 204   // max(1, int(2048*0.1))

// Scratch (device globals: no runtime allocation allowed)
__device__ float g_qkv[(size_t)Bc * Sc * E3];    // [B,S,3E]
__device__ float g_attn[(size_t)Bc * Sc * Ec];   // [B,S,H*D]
__device__ int   g_gcol[Sc];

// ---------------------------------------------------------------------------
// Global-column flags: emulate jnp.linspace(0, S-1, NGLOB).astype(int32)
// ---------------------------------------------------------------------------
__global__ void gcol_kernel() {
    int t = threadIdx.x;
    for (int j = t; j < Sc; j += blockDim.x) g_gcol[j] = 0;
    __syncthreads();
    const float step = (float)((double)(Sc - 1) / (double)(NGLOB - 1));
    for (int k = t; k < NGLOB; k += blockDim.x) {
        int pos;
        if (k == NGLOB - 1) pos = Sc - 1;   // endpoint is exact in numpy/jax linspace
        else                pos = (int)(__fmul_rn((float)k, step));
        if (pos < 0) pos = 0;
        if (pos > Sc - 1) pos = Sc - 1;
        g_gcol[pos] = 1;
    }
}

// ---------------------------------------------------------------------------
// SGEMM with bias: C[M,N] = A[M,K] * W[K,N] + bias[N]
// BM=BN=128, BK=8, 256 threads, 8x8 microtile. Assumes M%128==0, N%128==0, K%8==0.
// ---------------------------------------------------------------------------
__global__ __launch_bounds__(256) void sgemm_bias(
    const float* __restrict__ A, const float* __restrict__ W,
    const float* __restrict__ bias, float* __restrict__ C,
    int M, int N, int K)
{
    __shared__ float As[8][128];   // transposed A tile
    __shared__ float Bs[8][128];

    const int tid = threadIdx.x;
    const int bx = blockIdx.x, by = blockIdx.y;
    const int tx = tid & 15, ty = tid >> 4;

    const float* Ab = A + (size_t)by * 128 * K;
    const float* Wb = W + (size_t)bx * 128;

    const int aRow = tid >> 1;             // 0..127
    const int aCol = (tid & 1) * 4;        // 0 or 4
    const int bRow = tid >> 5;             // 0..7
    const int bCol = (tid & 31) * 4;       // 0..124

    float acc[8][8];
#pragma unroll
    for (int i = 0; i < 8; i++)
#pragma unroll
        for (int j = 0; j < 8; j++) acc[i][j] = 0.f;

    for (int k0 = 0; k0 < K; k0 += 8) {
        float4 av = *(const float4*)(Ab + (size_t)aRow * K + k0 + aCol);
        As[aCol + 0][aRow] = av.x;
        As[aCol + 1][aRow] = av.y;
        As[aCol + 2][aRow] = av.z;
        As[aCol + 3][aRow] = av.w;
        *(float4*)&Bs[bRow][bCol] = *(const float4*)(Wb + (size_t)(k0 + bRow) * N + bCol);
        __syncthreads();

#pragma unroll
        for (int kk = 0; kk < 8; kk++) {
            float ar[8], br[8];
            *(float4*)&ar[0] = *(const float4*)&As[kk][ty * 8];
            *(float4*)&ar[4] = *(const float4*)&As[kk][ty * 8 + 4];
            *(float4*)&br[0] = *(const float4*)&Bs[kk][tx * 8];
            *(float4*)&br[4] = *(const float4*)&Bs[kk][tx * 8 + 4];
#pragma unroll
            for (int i = 0; i < 8; i++)
#pragma unroll
                for (int j = 0; j < 8; j++)
                    acc[i][j] += ar[i] * br[j];
        }
        __syncthreads();
    }

    float4 bv0 = *(const float4*)&bias[bx * 128 + tx * 8];
    float4 bv1 = *(const float4*)&bias[bx * 128 + tx * 8 + 4];
#pragma unroll
    for (int i = 0; i < 8; i++) {
        int row = by * 128 + ty * 8 + i;
        float* Cp = C + (size_t)row * N + bx * 128 + tx * 8;
        float4 o0 = make_float4(acc[i][0] + bv0.x, acc[i][1] + bv0.y,
                                acc[i][2] + bv0.z, acc[i][3] + bv0.w);
        float4 o1 = make_float4(acc[i][4] + bv1.x, acc[i][5] + bv1.y,
                                acc[i][6] + bv1.z, acc[i][7] + bv1.w);
        *(float4*)&Cp[0] = o0;
        *(float4*)&Cp[4] = o1;
    }
}

// ---------------------------------------------------------------------------
// Attention: one block = one (batch, head, 64-row query tile).
// Flash-style online softmax over 64-key tiles. fp32.
// heads 0..7 local window mask, heads 8..11 causal | global-column mask.
// ---------------------------------------------------------------------------
__global__ __launch_bounds__(256) void attn_kernel(
    const float* __restrict__ qkv, float* __restrict__ out, int half_w)
{
    __shared__ float qT[64][64];   // [d][row]
    __shared__ float kp[64 * 64];  // kT[d][key]  UNION  pT swizzled [key][*]
    __shared__ float vs[64][64];   // [key][d]

    const int qt = blockIdx.x, h = blockIdx.y, b = blockIdx.z;
    const bool is_local = (h < 8);
    const int q0 = qt << 6;
    const int tid = threadIdx.x;
    const int tx = tid & 15, ty = tid >> 4;
    const int tx4 = tx * 4, ty4 = ty * 4;

    const float* qb = qkv + (size_t)b * Sc * E3 + h * Dc;         // q at col offset 0
    const float* kb = qb + Ec;                                    // k
    const float* vb = qb + 2 * Ec;                                // v

    // Load Q tile transposed
#pragma unroll
    for (int i = 0; i < 4; i++) {
        int slot = tid + i * 256;
        int row = slot >> 4, d0 = (slot & 15) << 2;
        float4 v = *(const float4*)(qb + (size_t)(q0 + row) * E3 + d0);
        qT[d0 + 0][row] = v.x;
        qT[d0 + 1][row] = v.y;
        qT[d0 + 2][row] = v.z;
        qT[d0 + 3][row] = v.w;
    }

    float m[4], l[4], acc[4][4];
#pragma unroll
    for (int r = 0; r < 4; r++) {
        m[r] = -1e30f; l[r] = 0.f;
#pragma unroll
        for (int c = 0; c < 4; c++) acc[r][c] = 0.f;
    }

    int kt0, kt1;
    if (is_local) {
        int lo = (q0 - half_w) >> 6;
        kt0 = lo > 0 ? lo : 0;
        kt1 = qt;
    } else {
        kt0 = 0;
        kt1 = (Sc >> 6) - 1;
    }

    __syncthreads();

    const float scale = 0.125f;  // 1/sqrt(64)

    for (int kt = kt0; kt <= kt1; kt++) {
        const int k0 = kt << 6;

        // Load K transposed (into kp) and V natural
#pragma unroll
        for (int i = 0; i < 4; i++) {
            int slot = tid + i * 256;
            int row = slot >> 4, d0 = (slot & 15) << 2;
            float4 kv = *(const float4*)(kb + (size_t)(k0 + row) * E3 + d0);
            kp[(d0 + 0) * 64 + row] = kv.x;
            kp[(d0 + 1) * 64 + row] = kv.y;
            kp[(d0 + 2) * 64 + row] = kv.z;
            kp[(d0 + 3) * 64 + row] = kv.w;
            *(float4*)&vs[row][d0] = *(const float4*)(vb + (size_t)(k0 + row) * E3 + d0);
        }
        __syncthreads();

        // Scores: s[r][c] = q(row ty4+r) . k(key tx4+c)
        float s[4][4];
#pragma unroll
        for (int r = 0; r < 4; r++)
#pragma unroll
            for (int c = 0; c < 4; c++) s[r][c] = 0.f;

#pragma unroll 8
        for (int d = 0; d < 64; d++) {
            float4 a = *(const float4*)&qT[d][ty4];
            float4 bq = *(const float4*)&kp[d * 64 + tx4];
            float av[4] = {a.x, a.y, a.z, a.w};
            float bv[4] = {bq.x, bq.y, bq.z, bq.w};
#pragma unroll
            for (int r = 0; r < 4; r++)
#pragma unroll
                for (int c = 0; c < 4; c++)
                    s[r][c] += av[r] * bv[c];
        }
        __syncthreads();  // done reading kp as K^T; can reuse as P

        // Mask + scale
        int gf[4] = {0, 0, 0, 0};
        if (!is_local) {
#pragma unroll
            for (int c = 0; c < 4; c++) gf[c] = g_gcol[k0 + tx4 + c];
        }
#pragma unroll
        for (int r = 0; r < 4; r++) {
            int i = q0 + ty4 + r;
#pragma unroll
            for (int c = 0; c < 4; c++) {
                int j = k0 + tx4 + c;
                bool ok = is_local ? (j <= i && j >= i - half_w)
                                   : (j <= i || gf[c]);
                s[r][c] = ok ? s[r][c] * scale : -1e9f;
            }
        }

        // Online softmax (row stats reduced across the 16 tx lanes)
#pragma unroll
        for (int r = 0; r < 4; r++) {
            float tm = fmaxf(fmaxf(s[r][0], s[r][1]), fmaxf(s[r][2], s[r][3]));
            tm = fmaxf(tm, __shfl_xor_sync(0xffffffffu, tm, 8));
            tm = fmaxf(tm, __shfl_xor_sync(0xffffffffu, tm, 4));
            tm = fmaxf(tm, __shfl_xor_sync(0xffffffffu, tm, 2));
            tm = fmaxf(tm, __shfl_xor_sync(0xffffffffu, tm, 1));
            float mn = fmaxf(m[r], tm);
            float fac = __expf(m[r] - mn);
            m[r] = mn;
            l[r] *= fac;
            acc[r][0] *= fac; acc[r][1] *= fac; acc[r][2] *= fac; acc[r][3] *= fac;
            float ps = 0.f;
#pragma unroll
            for (int c = 0; c < 4; c++) {
                float p = __expf(s[r][c] - mn);
                ps += p;
                int key = tx4 + c;
                kp[key * 64 + ((ty4 + r + key) & 63)] = p;  // swizzled P store
            }
            ps += __shfl_xor_sync(0xffffffffu, ps, 8);
            ps += __shfl_xor_sync(0xffffffffu, ps, 4);
            ps += __shfl_xor_sync(0xffffffffu, ps, 2);
            ps += __shfl_xor_sync(0xffffffffu, ps, 1);
            l[r] += ps;
        }
        __syncthreads();

        // acc += P * V
#pragma unroll 8
        for (int k = 0; k < 64; k++) {
            float4 vv = *(const float4*)&vs[k][tx4];
            float p0 = kp[k * 64 + ((ty4 + 0 + k) & 63)];
            float p1 = kp[k * 64 + ((ty4 + 1 + k) & 63)];
            float p2 = kp[k * 64 + ((ty4 + 2 + k) & 63)];
            float p3 = kp[k * 64 + ((ty4 + 3 + k) & 63)];
            acc[0][0] += p0 * vv.x; acc[0][1] += p0 * vv.y; acc[0][2] += p0 * vv.z; acc[0][3] += p0 * vv.w;
            acc[1][0] += p1 * vv.x; acc[1][1] += p1 * vv.y; acc[1][2] += p1 * vv.z; acc[1][3] += p1 * vv.w;
            acc[2][0] += p2 * vv.x; acc[2][1] += p2 * vv.y; acc[2][2] += p2 * vv.z; acc[2][3] += p2 * vv.w;
            acc[3][0] += p3 * vv.x; acc[3][1] += p3 * vv.y; acc[3][2] += p3 * vv.z; acc[3][3] += p3 * vv.w;
        }
        __syncthreads();
    }

    // Write normalized output: layout [B, S, H*D]
#pragma unroll
    for (int r = 0; r < 4; r++) {
        float inv = 1.0f / l[r];
        float4 o = make_float4(acc[r][0] * inv, acc[r][1] * inv,
                               acc[r][2] * inv, acc[r][3] * inv);
        int row = q0 + ty4 + r;
        *(float4*)(out + (size_t)(b * Sc + row) * Ec + h * Dc + tx4) = o;
    }
}

// ---------------------------------------------------------------------------
extern "C" void kernel_launch(void* const* d_in, const int* in_sizes, int n_in,
                              void* d_out, int out_size) {
    const float* x      = (const float*)d_in[0];
    const float* w_attn = (const float*)d_in[1];
    const float* b_attn = (const float*)d_in[2];
    const float* w_proj = (const float*)d_in[3];
    const float* b_proj = (const float*)d_in[4];
    float* out = (float*)d_out;

    float *qkv_p = nullptr, *attn_p = nullptr;
    cudaGetSymbolAddress((void**)&qkv_p, g_qkv);
    cudaGetSymbolAddress((void**)&attn_p, g_attn);

    // dynamic window: w = int(128*sqrt(S/128)), clamp [32, 512]
    int w = (int)(128.0 * sqrt((double)Sc / 128.0));
    if (w < 32) w = 32;
    if (w > 512) w = 512;
    int half_w = w / 2;

    gcol_kernel<<<1, 256>>>();

    dim3 g1(E3 / 128, (Bc * Sc) / 128);
    sgemm_bias<<<g1, 256>>>(x, w_attn, b_attn, qkv_p, Bc * Sc, E3, Ec);

    dim3 ga(Sc / 64, Hc, Bc);
    attn_kernel<<<ga, 256>>>(qkv_p, attn_p, half_w);

    dim3 g2(Ec / 128, (Bc * Sc) / 128);
    sgemm_bias<<<g2, 256>>>(attn_p, w_proj, b_proj, out, Bc * Sc, Ec, Ec);
}

// round 2
// speedup vs baseline: 3.6370x; 3.6370x over previous
#include <cuda_runtime.h>
#include <math.h>

#define Bc 4
#define Sc 2048
#define Ec 768
#define Hc 12
#define Dc 64
#define E3 2304
#define NGLOB 204

// Scratch
__device__ float g_qkv[(size_t)Bc * Sc * E3];
__device__ float g_attn[(size_t)Bc * Sc * Ec];
__device__ int   g_gcol[Sc];

__device__ __forceinline__ unsigned f2tf(float x) {
    unsigned r;
    asm("cvt.rna.tf32.f32 %0, %1;" : "=r"(r) : "f"(x));
    return r;
}

__device__ __forceinline__ void mma_tf32(float* d, const unsigned* a, unsigned b0, unsigned b1) {
    asm volatile(
        "mma.sync.aligned.m16n8k8.row.col.f32.tf32.tf32.f32 "
        "{%0,%1,%2,%3}, {%4,%5,%6,%7}, {%8,%9}, {%0,%1,%2,%3};"
        : "+f"(d[0]), "+f"(d[1]), "+f"(d[2]), "+f"(d[3])
        : "r"(a[0]), "r"(a[1]), "r"(a[2]), "r"(a[3]), "r"(b0), "r"(b1));
}

// ---------------------------------------------------------------------------
__global__ void gcol_kernel() {
    int t = threadIdx.x;
    for (int j = t; j < Sc; j += blockDim.x) g_gcol[j] = 0;
    __syncthreads();
    const float step = (float)((double)(Sc - 1) / (double)(NGLOB - 1));
    for (int k = t; k < NGLOB; k += blockDim.x) {
        int pos;
        if (k == NGLOB - 1) pos = Sc - 1;
        else                pos = (int)(__fmul_rn((float)k, step));
        if (pos < 0) pos = 0;
        if (pos > Sc - 1) pos = Sc - 1;
        g_gcol[pos] = 1;
    }
}

// ---------------------------------------------------------------------------
// tf32 tensor-core GEMM: C[M,N] = A[M,K]*W[K,N] + bias.  M%128==0, N%128==0, K%32==0.
// 256 threads = 8 warps (4x2). Warp tile 32x64. BK=32.
// ---------------------------------------------------------------------------
__global__ __launch_bounds__(256) void gemm_tf32(
    const float* __restrict__ A, const float* __restrict__ W,
    const float* __restrict__ bias, float* __restrict__ C,
    int M, int N, int K)
{
    __shared__ unsigned As[128][36];   // [m][k], pad -> (4m+k)%32 conflict-free
    __shared__ unsigned Bs[32][136];   // [k][n], pad -> (8k+n)%32 conflict-free

    const int tid = threadIdx.x;
    const int lane = tid & 31;
    const int w = tid >> 5;
    const int g = lane >> 2, c = lane & 3;
    const int wm = (w & 3) * 32;
    const int wn = (w >> 2) * 64;
    const int bx = blockIdx.x, by = blockIdx.y;

    float acc[2][8][4];
#pragma unroll
    for (int mt = 0; mt < 2; mt++)
#pragma unroll
        for (int nt = 0; nt < 8; nt++)
#pragma unroll
            for (int i = 0; i < 4; i++) acc[mt][nt][i] = 0.f;

    for (int k0 = 0; k0 < K; k0 += 32) {
        // load A tile 128x32
#pragma unroll
        for (int i = 0; i < 4; i++) {
            int idx = tid + i * 256;
            int row = idx >> 3, kc = (idx & 7) << 2;
            float4 v = *(const float4*)(A + (size_t)(by * 128 + row) * K + k0 + kc);
            uint4 u = make_uint4(f2tf(v.x), f2tf(v.y), f2tf(v.z), f2tf(v.w));
            *(uint4*)&As[row][kc] = u;
        }
        // load B tile 32x128
#pragma unroll
        for (int i = 0; i < 4; i++) {
            int idx = tid + i * 256;
            int kr = idx >> 5, nc = (idx & 31) << 2;
            float4 v = *(const float4*)(W + (size_t)(k0 + kr) * N + bx * 128 + nc);
            uint4 u = make_uint4(f2tf(v.x), f2tf(v.y), f2tf(v.z), f2tf(v.w));
            *(uint4*)&Bs[kr][nc] = u;
        }
        __syncthreads();

#pragma unroll
        for (int ks = 0; ks < 4; ks++) {
            const int kk = ks * 8;
            unsigned a[2][4];
#pragma unroll
            for (int mt = 0; mt < 2; mt++) {
                int m = wm + mt * 16 + g;
                a[mt][0] = As[m][kk + c];
                a[mt][1] = As[m + 8][kk + c];
                a[mt][2] = As[m][kk + c + 4];
                a[mt][3] = As[m + 8][kk + c + 4];
            }
#pragma unroll
            for (int nt = 0; nt < 8; nt++) {
                unsigned b0 = Bs[kk + c][wn + nt * 8 + g];
                unsigned b1 = Bs[kk + c + 4][wn + nt * 8 + g];
#pragma unroll
                for (int mt = 0; mt < 2; mt++)
                    mma_tf32(acc[mt][nt], a[mt], b0, b1);
            }
        }
        __syncthreads();
    }

    // epilogue
#pragma unroll
    for (int mt = 0; mt < 2; mt++) {
        int r0 = by * 128 + wm + mt * 16 + g;
#pragma unroll
        for (int nt = 0; nt < 8; nt++) {
            int col = bx * 128 + wn + nt * 8 + 2 * c;
            float bv0 = bias[col], bv1 = bias[col + 1];
            float2 o0 = make_float2(acc[mt][nt][0] + bv0, acc[mt][nt][1] + bv1);
            float2 o1 = make_float2(acc[mt][nt][2] + bv0, acc[mt][nt][3] + bv1);
            *(float2*)(C + (size_t)r0 * N + col) = o0;
            *(float2*)(C + (size_t)(r0 + 8) * N + col) = o1;
        }
    }
}

// ---------------------------------------------------------------------------
// Tensor-core attention: block = (qtile64, head, batch); 4 warps x 16 q-rows.
// Keys stored with pi-permutation so QK accumulator layout == PV A-fragment.
// ---------------------------------------------------------------------------
__global__ __launch_bounds__(128) void attn_tc(
    const float* __restrict__ qkv, float* __restrict__ out, int half_w)
{
    __shared__ unsigned Ks[64][68];  // permuted slot -> (4s+d)%32 conflict-free
    __shared__ unsigned Vs[64][72];  // natural key  -> (8k+d)%32 conflict-free
    __shared__ int Gs[64];

    const int qt = blockIdx.x, h = blockIdx.y, b = blockIdx.z;
    const bool is_local = (h < 8);
    const int q0 = qt << 6;
    const int tid = threadIdx.x;
    const int lane = tid & 31;
    const int w = tid >> 5;
    const int g = lane >> 2, c = lane & 3;

    const float* qb = qkv + (size_t)b * Sc * E3 + h * Dc;
    const float* kb = qb + Ec;
    const float* vb = qb + 2 * Ec;

    // Q fragments in registers (pre-scaled by 1/sqrt(D), rna->tf32)
    const int r0 = q0 + 16 * w + g;
    const float* qrow0 = qb + (size_t)r0 * E3;
    const float* qrow1 = qrow0 + (size_t)8 * E3;
    unsigned qa[8][4];
#pragma unroll
    for (int ks = 0; ks < 8; ks++) {
        qa[ks][0] = f2tf(qrow0[ks * 8 + c] * 0.125f);
        qa[ks][1] = f2tf(qrow1[ks * 8 + c] * 0.125f);
        qa[ks][2] = f2tf(qrow0[ks * 8 + c + 4] * 0.125f);
        qa[ks][3] = f2tf(qrow1[ks * 8 + c + 4] * 0.125f);
    }

    float o[8][4];
#pragma unroll
    for (int nt = 0; nt < 8; nt++)
#pragma unroll
        for (int i = 0; i < 4; i++) o[nt][i] = 0.f;
    float m0 = -1e30f, m1 = -1e30f, l0 = 0.f, l1 = 0.f;

    int kt0, kt1;
    if (is_local) {
        int lo = (q0 - half_w) >> 6;
        kt0 = lo > 0 ? lo : 0;
        kt1 = qt;
    } else {
        kt0 = 0;
        kt1 = (Sc >> 6) - 1;
    }

    for (int kt = kt0; kt <= kt1; kt++) {
        const int k0 = kt << 6;
        __syncthreads();   // prior PV reads done before overwriting K/V

        if (tid < 64) Gs[tid] = g_gcol[k0 + tid];
#pragma unroll
        for (int i = 0; i < 8; i++) {
            int idx = tid + i * 128;
            int slot = idx >> 4, dc = (idx & 15) << 2;
            // K: permuted slot -> key  (pi(x) = (x>>1) + 4*(x&1))
            int jk = k0 + (slot & 56) + ((slot & 7) >> 1) + ((slot & 1) << 2);
            float4 kv = *(const float4*)(kb + (size_t)jk * E3 + dc);
            *(uint4*)&Ks[slot][dc] = make_uint4(f2tf(kv.x), f2tf(kv.y), f2tf(kv.z), f2tf(kv.w));
            // V: natural order
            float4 vv = *(const float4*)(vb + (size_t)(k0 + slot) * E3 + dc);
            *(uint4*)&Vs[slot][dc] = make_uint4(f2tf(vv.x), f2tf(vv.y), f2tf(vv.z), f2tf(vv.w));
        }
        __syncthreads();

        // QK^T
        float s[8][4];
#pragma unroll
        for (int nt = 0; nt < 8; nt++)
#pragma unroll
            for (int i = 0; i < 4; i++) s[nt][i] = 0.f;
#pragma unroll
        for (int ks = 0; ks < 8; ks++) {
            const int kk = ks * 8;
#pragma unroll
            for (int nt = 0; nt < 8; nt++) {
                unsigned b0 = Ks[nt * 8 + g][kk + c];
                unsigned b1 = Ks[nt * 8 + g][kk + c + 4];
                mma_tf32(s[nt], qa[ks], b0, b1);
            }
        }

        // mask (c0: key jA row r0, c1: key jB row r0, c2: jA r1, c3: jB r1)
        const int r1 = r0 + 8;
#pragma unroll
        for (int nt = 0; nt < 8; nt++) {
            int jA = k0 + 8 * nt + c;
            int jB = jA + 4;
            bool okA0, okB0, okA1, okB1;
            if (is_local) {
                okA0 = (jA <= r0) && (jA >= r0 - half_w);
                okB0 = (jB <= r0) && (jB >= r0 - half_w);
                okA1 = (jA <= r1) && (jA >= r1 - half_w);
                okB1 = (jB <= r1) && (jB >= r1 - half_w);
            } else {
                int gA = Gs[8 * nt + c], gB = Gs[8 * nt + c + 4];
                okA0 = (jA <= r0) || gA;
                okB0 = (jB <= r0) || gB;
                okA1 = (jA <= r1) || gA;
                okB1 = (jB <= r1) || gB;
            }
            s[nt][0] = okA0 ? s[nt][0] : -1e9f;
            s[nt][1] = okB0 ? s[nt][1] : -1e9f;
            s[nt][2] = okA1 ? s[nt][2] : -1e9f;
            s[nt][3] = okB1 ? s[nt][3] : -1e9f;
        }

        // online softmax (rows r0: regs 0,1 ; r1: regs 2,3), reduce over 4 lanes
        float mx0 = -1e30f, mx1 = -1e30f;
#pragma unroll
        for (int nt = 0; nt < 8; nt++) {
            mx0 = fmaxf(mx0, fmaxf(s[nt][0], s[nt][1]));
            mx1 = fmaxf(mx1, fmaxf(s[nt][2], s[nt][3]));
        }
        mx0 = fmaxf(mx0, __shfl_xor_sync(0xffffffffu, mx0, 1));
        mx0 = fmaxf(mx0, __shfl_xor_sync(0xffffffffu, mx0, 2));
        mx1 = fmaxf(mx1, __shfl_xor_sync(0xffffffffu, mx1, 1));
        mx1 = fmaxf(mx1, __shfl_xor_sync(0xffffffffu, mx1, 2));

        float mn0 = fmaxf(m0, mx0), mn1 = fmaxf(m1, mx1);
        float f0 = __expf(m0 - mn0), f1 = __expf(m1 - mn1);
        m0 = mn0; m1 = mn1;

        float ps0 = 0.f, ps1 = 0.f;
#pragma unroll
        for (int nt = 0; nt < 8; nt++) {
            s[nt][0] = __expf(s[nt][0] - mn0);
            s[nt][1] = __expf(s[nt][1] - mn0);
            s[nt][2] = __expf(s[nt][2] - mn1);
            s[nt][3] = __expf(s[nt][3] - mn1);
            ps0 += s[nt][0] + s[nt][1];
            ps1 += s[nt][2] + s[nt][3];
            o[nt][0] *= f0; o[nt][1] *= f0;
            o[nt][2] *= f1; o[nt][3] *= f1;
        }
        ps0 += __shfl_xor_sync(0xffffffffu, ps0, 1);
        ps0 += __shfl_xor_sync(0xffffffffu, ps0, 2);
        ps1 += __shfl_xor_sync(0xffffffffu, ps1, 1);
        ps1 += __shfl_xor_sync(0xffffffffu, ps1, 2);
        l0 = l0 * f0 + ps0;
        l1 = l1 * f1 + ps1;

        // PV: P fragments come straight from score regs (interleave trick)
#pragma unroll
        for (int ktile = 0; ktile < 8; ktile++) {
            unsigned pa[4];
            pa[0] = f2tf(s[ktile][0]);
            pa[1] = f2tf(s[ktile][2]);
            pa[2] = f2tf(s[ktile][1]);
            pa[3] = f2tf(s[ktile][3]);
#pragma unroll
            for (int nt = 0; nt < 8; nt++) {
                unsigned b0 = Vs[8 * ktile + c][8 * nt + g];
                unsigned b1 = Vs[8 * ktile + c + 4][8 * nt + g];
                mma_tf32(o[nt], pa, b0, b1);
            }
        }
    }

    // write [B,S,H*D]
    float inv0 = 1.0f / l0, inv1 = 1.0f / l1;
    float* ob0 = out + (size_t)(b * Sc + r0) * Ec + h * Dc;
    float* ob1 = out + (size_t)(b * Sc + r0 + 8) * Ec + h * Dc;
#pragma unroll
    for (int nt = 0; nt < 8; nt++) {
        int d = 8 * nt + 2 * c;
        *(float2*)(ob0 + d) = make_float2(o[nt][0] * inv0, o[nt][1] * inv0);
        *(float2*)(ob1 + d) = make_float2(o[nt][2] * inv1, o[nt][3] * inv1);
    }
}

// ---------------------------------------------------------------------------
extern "C" void kernel_launch(void* const* d_in, const int* in_sizes, int n_in,
                              void* d_out, int out_size) {
    const float* x      = (const float*)d_in[0];
    const float* w_attn = (const float*)d_in[1];
    const float* b_attn = (const float*)d_in[2];
    const float* w_proj = (const float*)d_in[3];
    const float* b_proj = (const float*)d_in[4];
    float* out = (float*)d_out;

    float *qkv_p = nullptr, *attn_p = nullptr;
    cudaGetSymbolAddress((void**)&qkv_p, g_qkv);
    cudaGetSymbolAddress((void**)&attn_p, g_attn);

    int wdw = (int)(128.0 * sqrt((double)Sc / 128.0));
    if (wdw < 32) wdw = 32;
    if (wdw > 512) wdw = 512;
    int half_w = wdw / 2;

    gcol_kernel<<<1, 256>>>();

    dim3 g1(E3 / 128, (Bc * Sc) / 128);
    gemm_tf32<<<g1, 256>>>(x, w_attn, b_attn, qkv_p, Bc * Sc, E3, Ec);

    dim3 ga(Sc / 64, Hc, Bc);
    attn_tc<<<ga, 128>>>(qkv_p, attn_p, half_w);

    dim3 g2(Ec / 128, (Bc * Sc) / 128);
    gemm_tf32<<<g2, 256>>>(attn_p, w_proj, b_proj, out, Bc * Sc, Ec, Ec);
}